// round 15
// baseline (speedup 1.0000x reference)
#include <cuda_runtime.h>
#include <cuda_bf16.h>
#include <cstdint>

#define FULLM 0xffffffffu
constexpr int Bb = 128, Pp = 256, Hh = 512;
constexpr int KBIG = Pp * Hh;        // 131072
constexpr int J2 = 2 * Pp * 32;      // 16384
constexpr float EPSF = 1e-5f;
constexpr float ALPHAc = 0.9f;
constexpr float INV16TAU = 1.0f / (16.0f * 0.3f);
constexpr float LOG2E = 1.4426950408889634f;

// ---- mma.sync GEMM config ----
constexpr int KSTEP = 32;
constexpr int KSPLIT5 = 74;               // 4x74 = 296 CTAs = exactly 2/SM on 148 SMs
constexpr int APITCH = 80;                // bytes per 32-col bf16 row (padded)
constexpr int TILE_B = 128 * APITCH;      // 10240
constexpr int STAGE = 4 * TILE_B;         // Ah, Al, Wh, Wl = 40960
constexpr int SMEM_MMA = 2 * STAGE;       // 81920

__device__ float g_av[512], g_bv[512];
__device__ float g_qc1[Bb * 8 * Pp], g_qc0[Bb * 8 * Pp];
__device__ __align__(16) float4 g_ekv[Bb * 8 * Pp];   // (ek1, ek0, ev1, ev0)
__device__ float g_res[Bb * Hh];
__device__ __align__(16) __nv_bfloat16 g_h_hi[(long)Bb * Pp * Hh];
__device__ __align__(16) __nv_bfloat16 g_h_lo[(long)Bb * Pp * Hh];
__device__ float g_acc0[Bb * Hh];
__device__ __align__(16) __nv_bfloat16 g_z1_hi[Bb * Hh], g_z1_lo[Bb * Hh];
__device__ float g_z2[Bb * J2];

#define MMA16816(d, a, b0v, b1v) \
    asm volatile("mma.sync.aligned.m16n8k16.row.col.f32.bf16.bf16.f32 " \
        "{%0,%1,%2,%3}, {%4,%5,%6,%7}, {%8,%9}, {%0,%1,%2,%3};" \
        : "+f"((d)[0]), "+f"((d)[1]), "+f"((d)[2]), "+f"((d)[3]) \
        : "r"((a)[0]), "r"((a)[1]), "r"((a)[2]), "r"((a)[3]), "r"(b0v), "r"(b1v))

#define LDSM4(r0, r1, r2, r3, addr) \
    asm volatile("ldmatrix.sync.aligned.m8n8.x4.shared.b16 {%0,%1,%2,%3}, [%4];" \
        : "=r"(r0), "=r"(r1), "=r"(r2), "=r"(r3) : "r"(addr))

#define CPASYNC16(dst, src) \
    asm volatile("cp.async.ca.shared.global [%0], [%1], 16;" :: "r"(dst), "l"(src))
#define CPCOMMIT() asm volatile("cp.async.commit_group;" ::: "memory")
#define CPWAIT0()  asm volatile("cp.async.wait_group 0;" ::: "memory")

__device__ __forceinline__ uint32_t smem_u32(const void* p) {
    uint32_t a;
    asm("{ .reg .u64 t; cvta.to.shared.u64 t, %1; cvt.u32.u64 %0, t; }" : "=r"(a) : "l"(p));
    return a;
}
__device__ __forceinline__ float ex2f(float x) {
    float r;
    asm("ex2.approx.f32 %0, %1;" : "=f"(r) : "f"(x));
    return r;
}
__device__ __forceinline__ float wsum(float v) {
#pragma unroll
    for (int o = 16; o; o >>= 1) v += __shfl_xor_sync(FULLM, v, o);
    return v;
}

// ---------------- K01: per-head stats + tables (blocks 0..127) + res GEMV (128..8319) ----
__global__ __launch_bounds__(256) void k01(const float* __restrict__ X,
                                           const float* __restrict__ qw, const float* __restrict__ qb,
                                           const float* __restrict__ kw, const float* __restrict__ kb,
                                           const float* __restrict__ vw, const float* __restrict__ vb,
                                           const float* __restrict__ rw, const float* __restrict__ rb) {
    int bx = blockIdx.x;
    int t = threadIdx.x;
    int wid = t >> 5, lane = t & 31;

    if (bx >= 128) {   // res GEMV
        int o = (bx - 128) * 8 + wid;
        int b = o >> 9, c = o & 511;
        const float4* xr = (const float4*)(X + b * 256);
        const float4* wr = (const float4*)(rw + (long)c * 256);
        float acc = 0.f;
#pragma unroll
        for (int i = 0; i < 2; i++) {
            float4 xv = xr[lane + 32 * i];
            float4 wv = wr[lane + 32 * i];
            acc = fmaf(xv.x, wv.x, acc); acc = fmaf(xv.y, wv.y, acc);
            acc = fmaf(xv.z, wv.z, acc); acc = fmaf(xv.w, wv.w, acc);
        }
        acc = wsum(acc);
        if (lane == 0) g_res[b * 512 + c] = acc + rb[c];
        return;
    }

    __shared__ float ss[8 * 16];
    int b = bx;
    int h = wid;
    int c0 = h * 64 + lane, c1 = c0 + 32;

    float qw0 = qw[c0], qw1 = qw[c1], qb0 = qb[c0], qb1 = qb[c1];
    float kw0 = kw[c0], kw1 = kw[c1], kb0 = kb[c0], kb1 = kb[c1];
    float vw0 = vw[c0], vw1 = vw[c1], vb0 = vb[c0], vb1 = vb[c1];

    float muQw = wsum(qw0 + qw1) * (1.f / 64.f), muQb = wsum(qb0 + qb1) * (1.f / 64.f);
    float muKw = wsum(kw0 + kw1) * (1.f / 64.f), muKb = wsum(kb0 + kb1) * (1.f / 64.f);
    float muVw = wsum(vw0 + vw1) * (1.f / 64.f), muVb = wsum(vb0 + vb1) * (1.f / 64.f);

    float aq0 = qw0 - muQw, aq1 = qw1 - muQw, bq0 = qb0 - muQb, bq1 = qb1 - muQb;
    float ak0 = kw0 - muKw, ak1 = kw1 - muKw, bk0 = kb0 - muKb, bk1 = kb1 - muKb;
    float av0 = vw0 - muVw, av1 = vw1 - muVw, bv0 = vb0 - muVb, bv1 = vb1 - muVb;

    float A  = wsum(aq0 * ak0 + aq1 * ak1);
    float Bt = wsum(aq0 * bk0 + aq1 * bk1);
    float C  = wsum(bq0 * ak0 + bq1 * ak1);
    float D  = wsum(bq0 * bk0 + bq1 * bk1);
    float qV2 = wsum(aq0 * aq0 + aq1 * aq1) * (1.f / 64.f);
    float qV1 = wsum(aq0 * bq0 + aq1 * bq1) * (1.f / 64.f);
    float qV0 = wsum(bq0 * bq0 + bq1 * bq1) * (1.f / 64.f);
    float kV2 = wsum(ak0 * ak0 + ak1 * ak1) * (1.f / 64.f);
    float kV1 = wsum(ak0 * bk0 + ak1 * bk1) * (1.f / 64.f);
    float kV0 = wsum(bk0 * bk0 + bk1 * bk1) * (1.f / 64.f);
    float vV2 = wsum(av0 * av0 + av1 * av1) * (1.f / 64.f);
    float vV1 = wsum(av0 * bv0 + av1 * bv1) * (1.f / 64.f);
    float vV0 = wsum(bv0 * bv0 + bv1 * bv1) * (1.f / 64.f);

    if (lane == 0) {
        float* s = &ss[h * 16];
        s[0] = A; s[1] = Bt; s[2] = C; s[3] = D;
        s[4] = qV2; s[5] = 2.f * qV1; s[6] = qV0;
        s[7] = kV2; s[8] = 2.f * kV1; s[9] = kV0;
        s[10] = vV2; s[11] = 2.f * vV1; s[12] = vV0;
    }
    if (b == 0) {
        g_av[c0] = av0; g_av[c1] = av1;
        g_bv[c0] = bv0; g_bv[c1] = bv1;
    }
    __syncthreads();

    int p = t;
    float x = X[b * 256 + p];
#pragma unroll
    for (int hh = 0; hh < 8; hh++) {
        const float* s = &ss[hh * 16];
        int base = (b * 8 + hh) * 256 + p;
        float denq = sqrtf(fmaf(x, fmaf(x, s[4], s[5]), s[6]) + EPSF);
        float inv = (INV16TAU * LOG2E) / denq;
        g_qc1[base] = fmaf(s[0], x, s[2]) * inv;
        g_qc0[base] = fmaf(s[1], x, s[3]) * inv;
        float denk = sqrtf(fmaf(x, fmaf(x, s[7], s[8]), s[9]) + EPSF);
        float denv = sqrtf(fmaf(x, fmaf(x, s[10], s[11]), s[12]) + EPSF);
        g_ekv[base] = make_float4(x / denk, 1.f / denk, x / denv, 1.f / denv);
    }
    int i = b * 256 + p;
    g_acc0[i] = 0.f;
    g_acc0[i + 32768] = 0.f;
}

// ---------------- K23: attention + fused LN(h); 2 q-rows per warp ----------------
// grid 2048 (128 b x 16 q-blocks), 256 threads (8 warps, 2 q per warp).
__global__ __launch_bounds__(256) void k23(const float* __restrict__ lng,
                                           const float* __restrict__ lnb,
                                           float* __restrict__ outAttn) {
    __shared__ float4 sekv[2048];
    __shared__ float sav[512], sbv[512], sres[512];
    int bx = blockIdx.x;
    int t = threadIdx.x, warp = t >> 5, lane = t & 31;
    int b = bx >> 4;
    int q0 = (bx & 15) * 16 + warp * 2;
    int q1 = q0 + 1;

    for (int i = t; i < 2048; i += 256) sekv[i] = g_ekv[b * 2048 + i];
    if (t < 256) {
        sav[t] = g_av[t]; sav[t + 256] = g_av[t + 256];
        sbv[t] = g_bv[t]; sbv[t + 256] = g_bv[t + 256];
        sres[t] = g_res[b * 512 + t]; sres[t + 256] = g_res[b * 512 + t + 256];
    }
    __syncthreads();

    float macc0[8], macc1[8];
#pragma unroll
    for (int i = 0; i < 8; i++) { macc0[i] = 0.f; macc1[i] = 0.f; }
    float wv1a0[8], wv0a0[8], wv1a1[8], wv0a1[8];

#pragma unroll 1
    for (int h = 0; h < 8; h++) {
        int rbase = (b * 8 + h) * 256;
        float c1_0 = g_qc1[rbase + q0], c0_0 = g_qc0[rbase + q0];
        float c1_1 = g_qc1[rbase + q1], c0_1 = g_qc0[rbase + q1];
        const float4* ekv = sekv + h * 256;

        float e0[8], e1[8];
        float Z0 = 0.f, S10 = 0.f, S00 = 0.f;
        float Z1 = 0.f, S11 = 0.f, S01 = 0.f;
#pragma unroll
        for (int i = 0; i < 8; i++) {
            int k = lane + 32 * i;
            float4 kv = ekv[k];
            float a0 = fmaf(c1_0, kv.x, c0_0 * kv.y);
            float a1 = fmaf(c1_1, kv.x, c0_1 * kv.y);
            float ex0 = ex2f(a0);
            float ex1 = ex2f(a1);
            e0[i] = ex0; e1[i] = ex1;
            Z0 += ex0; Z1 += ex1;
            S10 = fmaf(ex0, kv.z, S10); S11 = fmaf(ex1, kv.z, S11);
            S00 = fmaf(ex0, kv.w, S00); S01 = fmaf(ex1, kv.w, S01);
        }
#pragma unroll
        for (int o = 16; o; o >>= 1) {
            Z0  += __shfl_xor_sync(FULLM, Z0, o);
            S10 += __shfl_xor_sync(FULLM, S10, o);
            S00 += __shfl_xor_sync(FULLM, S00, o);
            Z1  += __shfl_xor_sync(FULLM, Z1, o);
            S11 += __shfl_xor_sync(FULLM, S11, o);
            S01 += __shfl_xor_sync(FULLM, S01, o);
        }
        float iZ0 = 1.0f / Z0, iZ1 = 1.0f / Z1;
        wv1a0[h] = S10 * iZ0; wv0a0[h] = S00 * iZ0;
        wv1a1[h] = S11 * iZ1; wv0a1[h] = S01 * iZ1;
#pragma unroll
        for (int i = 0; i < 8; i++) {
            macc0[i] = fmaf(e0[i], iZ0, macc0[i]);
            macc1[i] = fmaf(e1[i], iZ1, macc1[i]);
        }
    }
    float* orow0 = outAttn + ((long)(b * 256) + q0) * 256;
    float* orow1 = outAttn + ((long)(b * 256) + q1) * 256;
#pragma unroll
    for (int i = 0; i < 8; i++) {
        orow0[lane + 32 * i] = macc0[i] * 0.125f;
        orow1[lane + 32 * i] = macc1[i] * 0.125f;
    }

    // ---- fused LN for q0, then q1 ----
#pragma unroll 1
    for (int sel = 0; sel < 2; sel++) {
        const float* wv1arr = sel ? wv1a1 : wv1a0;
        const float* wv0arr = sel ? wv0a1 : wv0a0;
        int q = sel ? q1 : q0;
        float tv[16];
        float s = 0.f, qq = 0.f;
#pragma unroll
        for (int ch = 0; ch < 16; ch++) {
            int c = ch * 32 + lane;
            int hh = ch >> 1;
            float v = fmaf(sav[c], wv1arr[hh], fmaf(sbv[c], wv0arr[hh], ALPHAc * sres[c]));
            tv[ch] = v;
            s += v;
            qq = fmaf(v, v, qq);
        }
#pragma unroll
        for (int o = 16; o; o >>= 1) {
            s  += __shfl_xor_sync(FULLM, s, o);
            qq += __shfl_xor_sync(FULLM, qq, o);
        }
        float mean = s * (1.f / 512.f);
        float var = qq * (1.f / 512.f) - mean * mean;
        float r = rsqrtf(var + EPSF);

        long rowbase = ((long)(b * 256) + q) * 512;
#pragma unroll
        for (int ch = 0; ch < 16; ch++) {
            int c = ch * 32 + lane;
            float o0 = fmaf((tv[ch] - mean) * r, lng[c], lnb[c]);
            __nv_bfloat16 hv = __float2bfloat16_rn(o0);
            float e = o0 - __bfloat162float(hv);
            g_h_hi[rowbase + c] = hv;
            g_h_lo[rowbase + c] = __float2bfloat16_rn(e);
        }
    }
}

// ---------------- 3-split bf16 mma.sync GEMM body (R9 geometry) ----------------
template<bool ATOMIC>
__device__ __forceinline__ void mma3_gemm(
    const __nv_bfloat16* __restrict__ Ahi, const __nv_bfloat16* __restrict__ Alo,
    const float* __restrict__ W, long Ksrc,
    float* __restrict__ Cout, int Cstride, const float* __restrict__ bias,
    int n0, long kbase, int nsteps)
{
    extern __shared__ char smem[];
    uint32_t sbase = smem_u32(smem);
    int t = threadIdx.x;
    int wid = t >> 5, lane = t & 31;
    int g = lane >> 2, tp = lane & 3;
    int warpM = wid >> 1, warpN = wid & 1;

    float acc[2][8][4];
#pragma unroll
    for (int a = 0; a < 2; a++)
#pragma unroll
        for (int b = 0; b < 8; b++)
#pragma unroll
            for (int c = 0; c < 4; c++) acc[a][b][c] = 0.f;

    float4 pw[4];

    auto cpasyncA = [&](long kg, uint32_t bufu) {
#pragma unroll
        for (int i = 0; i < 2; i++) {
            int c = i * 256 + t;
            int row = c >> 2, kc = c & 3;
            long gi = (long)row * Ksrc + kg + kc * 8;
            uint32_t dst = bufu + row * APITCH + kc * 16;
            CPASYNC16(dst, (const char*)(Ahi + gi));
            CPASYNC16(dst + TILE_B, (const char*)(Alo + gi));
        }
    };
    auto prefetchW = [&](long kg) {
#pragma unroll
        for (int i = 0; i < 4; i++) {
            int f = i * 256 + t;
            int row = f >> 3, kc = f & 7;
            pw[i] = *(const float4*)(W + (long)(n0 + row) * Ksrc + kg + kc * 4);
        }
    };
    auto storeW = [&](char* buf) {
#pragma unroll
        for (int i = 0; i < 4; i++) {
            int f = i * 256 + t;
            int row = f >> 3, kc = f & 7;
            float4 v = pw[i];
            __nv_bfloat162 h0 = __floats2bfloat162_rn(v.x, v.y);
            __nv_bfloat162 h1 = __floats2bfloat162_rn(v.z, v.w);
            float e0 = v.x - __bfloat162float(h0.x);
            float e1 = v.y - __bfloat162float(h0.y);
            float e2 = v.z - __bfloat162float(h1.x);
            float e3 = v.w - __bfloat162float(h1.y);
            __nv_bfloat162 l0 = __floats2bfloat162_rn(e0, e1);
            __nv_bfloat162 l1 = __floats2bfloat162_rn(e2, e3);
            *(uint2*)(buf + 2 * TILE_B + row * APITCH + kc * 8) =
                make_uint2(*(uint32_t*)&h0, *(uint32_t*)&h1);
            *(uint2*)(buf + 3 * TILE_B + row * APITCH + kc * 8) =
                make_uint2(*(uint32_t*)&l0, *(uint32_t*)&l1);
        }
    };

    const uint32_t aoff = (uint32_t)(lane & 15) * APITCH + ((lane >> 4) & 1) * 16;
    const uint32_t boff = (uint32_t)((lane & 7) + ((lane >> 4) & 1) * 8) * APITCH +
                          ((lane >> 3) & 1) * 16;

    cpasyncA(kbase, sbase);
    CPCOMMIT();
    prefetchW(kbase);
    storeW(smem);
    CPWAIT0();
    __syncthreads();

#pragma unroll 1
    for (int s = 0; s < nsteps; s++) {
        bool more = (s + 1 < nsteps);
        if (more) {
            cpasyncA(kbase + (long)(s + 1) * KSTEP, sbase + ((s + 1) & 1) * STAGE);
            CPCOMMIT();
            prefetchW(kbase + (long)(s + 1) * KSTEP);
        }
        uint32_t bufu = sbase + (s & 1) * STAGE;
        uint32_t aBase = bufu + (uint32_t)(warpM * 32) * APITCH + aoff;
        uint32_t bBase = bufu + 2 * TILE_B + (uint32_t)(warpN * 64) * APITCH + boff;

#pragma unroll
        for (int kt = 0; kt < 2; kt++) {
            uint32_t kb = kt * 32;
            uint32_t ah[2][4], al[2][4];
#pragma unroll
            for (int mt = 0; mt < 2; mt++) {
                uint32_t aa = aBase + (uint32_t)(mt * 16) * APITCH + kb;
                LDSM4(ah[mt][0], ah[mt][1], ah[mt][2], ah[mt][3], aa);
                LDSM4(al[mt][0], al[mt][1], al[mt][2], al[mt][3], aa + TILE_B);
            }
#pragma unroll
            for (int pr = 0; pr < 4; pr++) {
                uint32_t ba = bBase + (uint32_t)(pr * 16) * APITCH + kb;
                uint32_t b0, b1, b2, b3, c0r, c1r, c2r, c3r;
                LDSM4(b0, b1, b2, b3, ba);               // hi
                LDSM4(c0r, c1r, c2r, c3r, ba + TILE_B);  // lo
#pragma unroll
                for (int mt = 0; mt < 2; mt++) {
                    MMA16816(acc[mt][2 * pr],     ah[mt], b0, b1);
                    MMA16816(acc[mt][2 * pr],     ah[mt], c0r, c1r);
                    MMA16816(acc[mt][2 * pr],     al[mt], b0, b1);
                    MMA16816(acc[mt][2 * pr + 1], ah[mt], b2, b3);
                    MMA16816(acc[mt][2 * pr + 1], ah[mt], c2r, c3r);
                    MMA16816(acc[mt][2 * pr + 1], al[mt], b2, b3);
                }
            }
        }
        if (more) {
            storeW(smem + ((s + 1) & 1) * STAGE);
            CPWAIT0();
        }
        __syncthreads();
    }

#pragma unroll
    for (int mt = 0; mt < 2; mt++)
#pragma unroll
        for (int nt = 0; nt < 8; nt++) {
            int row = warpM * 32 + mt * 16 + g;
            int col = n0 + warpN * 64 + nt * 8 + tp * 2;
            if (ATOMIC) {
                atomicAdd(&Cout[(long)row * Cstride + col],           acc[mt][nt][0]);
                atomicAdd(&Cout[(long)row * Cstride + col + 1],       acc[mt][nt][1]);
                atomicAdd(&Cout[(long)(row + 8) * Cstride + col],     acc[mt][nt][2]);
                atomicAdd(&Cout[(long)(row + 8) * Cstride + col + 1], acc[mt][nt][3]);
            } else {
                Cout[(long)row * Cstride + col]           = acc[mt][nt][0] + bias[col];
                Cout[(long)row * Cstride + col + 1]       = acc[mt][nt][1] + bias[col + 1];
                Cout[(long)(row + 8) * Cstride + col]     = acc[mt][nt][2] + bias[col];
                Cout[(long)(row + 8) * Cstride + col + 1] = acc[mt][nt][3] + bias[col + 1];
            }
        }
}

// 4096 total K-steps split unevenly over 74 chunks: first 26 CTAs get 56, rest get 55.
__global__ __launch_bounds__(256, 2) void k5_mma(const float* __restrict__ w0) {
    int y = blockIdx.y;
    int nst = 55 + (y < 26 ? 1 : 0);
    long kb = ((long)y * 55 + (y < 26 ? y : 26)) * KSTEP;
    mma3_gemm<true>(g_h_hi, g_h_lo, w0, KBIG, g_acc0, Hh, nullptr,
                    blockIdx.x * 128, kb, nst);
}
__global__ __launch_bounds__(256, 2) void k7_mma(const float* __restrict__ w2,
                                                 const float* __restrict__ bb2) {
    mma3_gemm<false>(g_z1_hi, g_z1_lo, w2, Hh, g_z2, J2, bb2,
                     blockIdx.x * 128, 0, Hh / KSTEP);
}

// k6: tiled GEMV batch. Block = 16(b) x 8(j); z0 = relu(acc0+bb0) built in smem once.
__global__ __launch_bounds__(256) void k6_gemm1(const float* __restrict__ w1,
                                                const float* __restrict__ bb0,
                                                const float* __restrict__ bb1) {
    __shared__ float sz0[16][512];
    int jg = blockIdx.x, bg = blockIdx.y;
    int t = threadIdx.x, w = t >> 5, lane = t & 31;

    const float4* bz = (const float4*)bb0;
#pragma unroll
    for (int i = 0; i < 8; i++) {
        int idx = i * 256 + t;
        int row = idx >> 7, c4 = idx & 127;
        float4 av = *(const float4*)(g_acc0 + (long)(bg * 16 + row) * 512 + c4 * 4);
        float4 bv = bz[c4];
        float4 z;
        z.x = fmaxf(av.x + bv.x, 0.f);
        z.y = fmaxf(av.y + bv.y, 0.f);
        z.z = fmaxf(av.z + bv.z, 0.f);
        z.w = fmaxf(av.w + bv.w, 0.f);
        *(float4*)&sz0[row][c4 * 4] = z;
    }
    __syncthreads();

    int j = jg * 8 + w;
    float4 wreg[4];
    const float4* wrow = (const float4*)(w1 + (long)j * 512);
#pragma unroll
    for (int i = 0; i < 4; i++) wreg[i] = wrow[lane + 32 * i];
    float bj = bb1[j];

#pragma unroll 1
    for (int b = 0; b < 16; b++) {
        float acc = 0.f;
#pragma unroll
        for (int i = 0; i < 4; i++) {
            float4 zv = *(const float4*)&sz0[b][(lane + 32 * i) * 4];
            acc = fmaf(zv.x, wreg[i].x, acc);
            acc = fmaf(zv.y, wreg[i].y, acc);
            acc = fmaf(zv.z, wreg[i].z, acc);
            acc = fmaf(zv.w, wreg[i].w, acc);
        }
        acc = wsum(acc);
        if (lane == 0) {
            float v = fmaxf(acc + bj, 0.f);
            __nv_bfloat16 hv = __float2bfloat16_rn(v);
            float e = v - __bfloat162float(hv);
            int o = (bg * 16 + b) * 512 + j;
            g_z1_hi[o] = hv;
            g_z1_lo[o] = __float2bfloat16_rn(e);
        }
    }
}

// k8: coeffs = U @ V^T per batch. Vt stride 257 (conflict-free).
__global__ __launch_bounds__(256) void k8_coeffs(float* __restrict__ out) {
    __shared__ float Us[16 * 32];
    __shared__ float Vt[32 * 257];
    int b = blockIdx.x, i0 = blockIdx.y * 16, t = threadIdx.x;
    const float* src = g_z2 + (long)b * J2;
#pragma unroll
    for (int q = 0; q < 2; q++) Us[t + 256 * q] = src[i0 * 32 + t + 256 * q];
#pragma unroll
    for (int q = 0; q < 32; q++) {
        int idx = t + 256 * q;
        float v = src[8192 + idx];
        Vt[(idx & 31) * 257 + (idx >> 5)] = v;
    }
    __syncthreads();
    float acc[16];
#pragma unroll
    for (int i = 0; i < 16; i++) acc[i] = 0.f;
#pragma unroll
    for (int r = 0; r < 32; r++) {
        float v = Vt[r * 257 + t];
#pragma unroll
        for (int i = 0; i < 16; i++) acc[i] = fmaf(Us[i * 32 + r], v, acc[i]);
    }
#pragma unroll
    for (int i = 0; i < 16; i++)
        out[((long)(b * 256) + (i0 + i)) * 256 + t] = acc[i];
}

extern "C" void kernel_launch(void* const* d_in, const int* in_sizes, int n_in,
                              void* d_out, int out_size) {
    const float* x     = (const float*)d_in[0];
    const float* qw    = (const float*)d_in[1];
    const float* qb    = (const float*)d_in[2];
    const float* kw    = (const float*)d_in[3];
    const float* kb    = (const float*)d_in[4];
    const float* vw    = (const float*)d_in[5];
    const float* vb    = (const float*)d_in[6];
    const float* res_w = (const float*)d_in[7];
    const float* res_b = (const float*)d_in[8];
    const float* ln_g  = (const float*)d_in[9];
    const float* ln_b  = (const float*)d_in[10];
    const float* w0    = (const float*)d_in[11];
    const float* bb0   = (const float*)d_in[12];
    const float* w1    = (const float*)d_in[13];
    const float* bb1   = (const float*)d_in[14];
    const float* w2    = (const float*)d_in[15];
    const float* bb2   = (const float*)d_in[16];

    float* out  = (float*)d_out;
    float* outC = out;                                // coeffs_k: (B,P,P)
    float* outA = out + (long)Bb * Pp * Pp;           // attn_mean: (B,P,P)

    cudaFuncSetAttribute(k5_mma, cudaFuncAttributeMaxDynamicSharedMemorySize, SMEM_MMA);
    cudaFuncSetAttribute(k7_mma, cudaFuncAttributeMaxDynamicSharedMemorySize, SMEM_MMA);

    k01<<<128 + 8192, 256>>>(x, qw, qb, kw, kb, vw, vb, res_w, res_b);
    k23<<<2048, 256>>>(ln_g, ln_b, outA);
    k5_mma<<<dim3(4, KSPLIT5), 256, SMEM_MMA>>>(w0);          // profiled slot (launch #3)
    k6_gemm1<<<dim3(64, 8), 256>>>(w1, bb0, bb1);
    k7_mma<<<dim3(J2 / 128, 1), 256, SMEM_MMA>>>(w2, bb2);
    k8_coeffs<<<dim3(Bb, Pp / 16), 256>>>(outC);
}

// round 16
// speedup vs baseline: 1.0461x; 1.0461x over previous
#include <cuda_runtime.h>
#include <cuda_bf16.h>
#include <cstdint>

#define FULLM 0xffffffffu
constexpr int Bb = 128, Pp = 256, Hh = 512;
constexpr int KBIG = Pp * Hh;        // 131072
constexpr int J2 = 2 * Pp * 32;      // 16384
constexpr float EPSF = 1e-5f;
constexpr float ALPHAc = 0.9f;
constexpr float INV16TAU = 1.0f / (16.0f * 0.3f);
constexpr float LOG2E = 1.4426950408889634f;

// ---- mma.sync GEMM config ----
constexpr int KSTEP = 32;
constexpr int KSPLIT5 = 74;               // 4x74 = 296 CTAs = exactly 2/SM on 148 SMs
constexpr int APITCH = 80;                // bytes per 32-col bf16 row (padded)
constexpr int TILE_B = 128 * APITCH;      // 10240
constexpr int STAGE = 4 * TILE_B;         // Ah, Al, Wh, Wl = 40960
constexpr int SMEM_MMA = 2 * STAGE;       // 81920

__device__ float g_av[512], g_bv[512];
__device__ float g_qc1[Bb * 8 * Pp], g_qc0[Bb * 8 * Pp];
__device__ __align__(16) float4 g_ekv[Bb * 8 * Pp];   // (ek1, ek0, ev1, ev0)
__device__ float g_res[Bb * Hh];
__device__ __align__(16) __nv_bfloat16 g_h_hi[(long)Bb * Pp * Hh];
__device__ __align__(16) __nv_bfloat16 g_h_lo[(long)Bb * Pp * Hh];
__device__ float g_acc0[Bb * Hh];
__device__ __align__(16) __nv_bfloat16 g_z1_hi[Bb * Hh], g_z1_lo[Bb * Hh];
__device__ float g_z2[Bb * J2];

#define MMA16816(d, a, b0v, b1v) \
    asm volatile("mma.sync.aligned.m16n8k16.row.col.f32.bf16.bf16.f32 " \
        "{%0,%1,%2,%3}, {%4,%5,%6,%7}, {%8,%9}, {%0,%1,%2,%3};" \
        : "+f"((d)[0]), "+f"((d)[1]), "+f"((d)[2]), "+f"((d)[3]) \
        : "r"((a)[0]), "r"((a)[1]), "r"((a)[2]), "r"((a)[3]), "r"(b0v), "r"(b1v))

#define LDSM4(r0, r1, r2, r3, addr) \
    asm volatile("ldmatrix.sync.aligned.m8n8.x4.shared.b16 {%0,%1,%2,%3}, [%4];" \
        : "=r"(r0), "=r"(r1), "=r"(r2), "=r"(r3) : "r"(addr))

#define CPASYNC16(dst, src) \
    asm volatile("cp.async.ca.shared.global [%0], [%1], 16;" :: "r"(dst), "l"(src))
#define CPCOMMIT() asm volatile("cp.async.commit_group;" ::: "memory")
#define CPWAIT0()  asm volatile("cp.async.wait_group 0;" ::: "memory")

__device__ __forceinline__ uint32_t smem_u32(const void* p) {
    uint32_t a;
    asm("{ .reg .u64 t; cvta.to.shared.u64 t, %1; cvt.u32.u64 %0, t; }" : "=r"(a) : "l"(p));
    return a;
}
__device__ __forceinline__ float ex2f(float x) {
    float r;
    asm("ex2.approx.f32 %0, %1;" : "=f"(r) : "f"(x));
    return r;
}
__device__ __forceinline__ float wsum(float v) {
#pragma unroll
    for (int o = 16; o; o >>= 1) v += __shfl_xor_sync(FULLM, v, o);
    return v;
}

// ---------------- K01: stats+tables (blocks 0..127) + tiled res GEMV (128..639) ----------
__global__ __launch_bounds__(256) void k01(const float* __restrict__ X,
                                           const float* __restrict__ qw, const float* __restrict__ qb,
                                           const float* __restrict__ kw, const float* __restrict__ kb,
                                           const float* __restrict__ vw, const float* __restrict__ vb,
                                           const float* __restrict__ rw, const float* __restrict__ rb) {
    __shared__ float sx[16][256];     // res branch (16 KB); stats branch uses first 128 floats
    int bx = blockIdx.x;
    int t = threadIdx.x;
    int wid = t >> 5, lane = t & 31;

    if (bx >= 128) {   // tiled res GEMV: res[16b x 8c] per block
        int idx = bx - 128;           // 0..511
        int bg = idx >> 6;            // 0..7  (16 b each)
        int jg = idx & 63;            // 0..63 (8 c each)
        // stage x tile: 16 rows x 256 floats
#pragma unroll
        for (int i = 0; i < 4; i++) {
            int e = i * 256 + t;      // 0..1023 float4 slots
            int row = e >> 6, c4 = e & 63;
            *(float4*)&sx[row][c4 * 4] =
                *(const float4*)(X + (long)(bg * 16 + row) * 256 + c4 * 4);
        }
        __syncthreads();
        int c = jg * 8 + wid;
        float4 wreg[2];
        const float4* wrow = (const float4*)(rw + (long)c * 256);
        wreg[0] = wrow[lane];
        wreg[1] = wrow[lane + 32];
        float bc = rb[c];
#pragma unroll 1
        for (int b = 0; b < 16; b++) {
            float acc = 0.f;
#pragma unroll
            for (int i = 0; i < 2; i++) {
                float4 xv = *(const float4*)&sx[b][(lane + 32 * i) * 4];
                acc = fmaf(xv.x, wreg[i].x, acc);
                acc = fmaf(xv.y, wreg[i].y, acc);
                acc = fmaf(xv.z, wreg[i].z, acc);
                acc = fmaf(xv.w, wreg[i].w, acc);
            }
            acc = wsum(acc);
            if (lane == 0) g_res[(bg * 16 + b) * 512 + c] = acc + bc;
        }
        return;
    }

    float* ss = &sx[0][0];   // reuse smem for 8x16 stats
    int b = bx;
    int h = wid;
    int c0 = h * 64 + lane, c1 = c0 + 32;

    float qw0 = qw[c0], qw1 = qw[c1], qb0 = qb[c0], qb1 = qb[c1];
    float kw0 = kw[c0], kw1 = kw[c1], kb0 = kb[c0], kb1 = kb[c1];
    float vw0 = vw[c0], vw1 = vw[c1], vb0 = vb[c0], vb1 = vb[c1];

    float muQw = wsum(qw0 + qw1) * (1.f / 64.f), muQb = wsum(qb0 + qb1) * (1.f / 64.f);
    float muKw = wsum(kw0 + kw1) * (1.f / 64.f), muKb = wsum(kb0 + kb1) * (1.f / 64.f);
    float muVw = wsum(vw0 + vw1) * (1.f / 64.f), muVb = wsum(vb0 + vb1) * (1.f / 64.f);

    float aq0 = qw0 - muQw, aq1 = qw1 - muQw, bq0 = qb0 - muQb, bq1 = qb1 - muQb;
    float ak0 = kw0 - muKw, ak1 = kw1 - muKw, bk0 = kb0 - muKb, bk1 = kb1 - muKb;
    float av0 = vw0 - muVw, av1 = vw1 - muVw, bv0 = vb0 - muVb, bv1 = vb1 - muVb;

    float A  = wsum(aq0 * ak0 + aq1 * ak1);
    float Bt = wsum(aq0 * bk0 + aq1 * bk1);
    float C  = wsum(bq0 * ak0 + bq1 * ak1);
    float D  = wsum(bq0 * bk0 + bq1 * bk1);
    float qV2 = wsum(aq0 * aq0 + aq1 * aq1) * (1.f / 64.f);
    float qV1 = wsum(aq0 * bq0 + aq1 * bq1) * (1.f / 64.f);
    float qV0 = wsum(bq0 * bq0 + bq1 * bq1) * (1.f / 64.f);
    float kV2 = wsum(ak0 * ak0 + ak1 * ak1) * (1.f / 64.f);
    float kV1 = wsum(ak0 * bk0 + ak1 * bk1) * (1.f / 64.f);
    float kV0 = wsum(bk0 * bk0 + bk1 * bk1) * (1.f / 64.f);
    float vV2 = wsum(av0 * av0 + av1 * av1) * (1.f / 64.f);
    float vV1 = wsum(av0 * bv0 + av1 * bv1) * (1.f / 64.f);
    float vV0 = wsum(bv0 * bv0 + bv1 * bv1) * (1.f / 64.f);

    if (lane == 0) {
        float* s = &ss[h * 16];
        s[0] = A; s[1] = Bt; s[2] = C; s[3] = D;
        s[4] = qV2; s[5] = 2.f * qV1; s[6] = qV0;
        s[7] = kV2; s[8] = 2.f * kV1; s[9] = kV0;
        s[10] = vV2; s[11] = 2.f * vV1; s[12] = vV0;
    }
    if (b == 0) {
        g_av[c0] = av0; g_av[c1] = av1;
        g_bv[c0] = bv0; g_bv[c1] = bv1;
    }
    __syncthreads();

    int p = t;
    float x = X[b * 256 + p];
#pragma unroll
    for (int hh = 0; hh < 8; hh++) {
        const float* s = &ss[hh * 16];
        int base = (b * 8 + hh) * 256 + p;
        float denq = sqrtf(fmaf(x, fmaf(x, s[4], s[5]), s[6]) + EPSF);
        float inv = (INV16TAU * LOG2E) / denq;
        g_qc1[base] = fmaf(s[0], x, s[2]) * inv;
        g_qc0[base] = fmaf(s[1], x, s[3]) * inv;
        float denk = sqrtf(fmaf(x, fmaf(x, s[7], s[8]), s[9]) + EPSF);
        float denv = sqrtf(fmaf(x, fmaf(x, s[10], s[11]), s[12]) + EPSF);
        g_ekv[base] = make_float4(x / denk, 1.f / denk, x / denv, 1.f / denv);
    }
    int i = b * 256 + p;
    g_acc0[i] = 0.f;
    g_acc0[i + 32768] = 0.f;
}

// ---------------- K23: attention + fused LN(h) -> bf16 hi/lo (R13 shape) ----------------
__global__ __launch_bounds__(512) void k23(const float* __restrict__ lng,
                                           const float* __restrict__ lnb,
                                           float* __restrict__ outAttn) {
    __shared__ float4 sekv[2048];
    __shared__ float sav[512], sbv[512], sres[512];
    int bx = blockIdx.x;
    int t = threadIdx.x, warp = t >> 5, lane = t & 31;
    int b = bx >> 4;
    int q = (bx & 15) * 16 + warp;

    for (int i = t; i < 2048; i += 512) sekv[i] = g_ekv[b * 2048 + i];
    if (t < 512) {
        sav[t] = g_av[t];
        sbv[t] = g_bv[t];
        sres[t] = g_res[b * 512 + t];
    }
    __syncthreads();

    float macc[8];
#pragma unroll
    for (int i = 0; i < 8; i++) macc[i] = 0.f;
    float wv1arr[8], wv0arr[8];

#pragma unroll 1
    for (int h = 0; h < 8; h++) {
        int rbase = (b * 8 + h) * 256;
        float c1 = g_qc1[rbase + q];
        float c0 = g_qc0[rbase + q];
        const float4* ekv = sekv + h * 256;

        float e[8];
        float Z = 0.f, S1 = 0.f, S0 = 0.f;
#pragma unroll
        for (int i = 0; i < 8; i++) {
            int k = lane + 32 * i;
            float4 kv = ekv[k];
            float a = fmaf(c1, kv.x, c0 * kv.y);
            float ex = ex2f(a);
            e[i] = ex;
            Z += ex;
            S1 = fmaf(ex, kv.z, S1);
            S0 = fmaf(ex, kv.w, S0);
        }
#pragma unroll
        for (int o = 16; o; o >>= 1) {
            Z  += __shfl_xor_sync(FULLM, Z, o);
            S1 += __shfl_xor_sync(FULLM, S1, o);
            S0 += __shfl_xor_sync(FULLM, S0, o);
        }
        float invZ = 1.0f / Z;
        wv1arr[h] = S1 * invZ;
        wv0arr[h] = S0 * invZ;
#pragma unroll
        for (int i = 0; i < 8; i++) macc[i] = fmaf(e[i], invZ, macc[i]);
    }
    float* orow = outAttn + ((long)(b * 256) + q) * 256;
#pragma unroll
    for (int i = 0; i < 8; i++) orow[lane + 32 * i] = macc[i] * 0.125f;

    // ---- fused LN over c for this (b, p=q) row ----
    float tv[16];
    float s = 0.f, qq = 0.f;
#pragma unroll
    for (int ch = 0; ch < 16; ch++) {
        int c = ch * 32 + lane;
        int hh = ch >> 1;
        float v = fmaf(sav[c], wv1arr[hh], fmaf(sbv[c], wv0arr[hh], ALPHAc * sres[c]));
        tv[ch] = v;
        s += v;
        qq = fmaf(v, v, qq);
    }
#pragma unroll
    for (int o = 16; o; o >>= 1) {
        s  += __shfl_xor_sync(FULLM, s, o);
        qq += __shfl_xor_sync(FULLM, qq, o);
    }
    float mean = s * (1.f / 512.f);
    float var = qq * (1.f / 512.f) - mean * mean;
    float r = rsqrtf(var + EPSF);

    long rowbase = ((long)(b * 256) + q) * 512;
#pragma unroll
    for (int ch = 0; ch < 16; ch++) {
        int c = ch * 32 + lane;
        float o0 = fmaf((tv[ch] - mean) * r, lng[c], lnb[c]);
        __nv_bfloat16 hv = __float2bfloat16_rn(o0);
        float e = o0 - __bfloat162float(hv);
        g_h_hi[rowbase + c] = hv;
        g_h_lo[rowbase + c] = __float2bfloat16_rn(e);
    }
}

// ---------------- 3-split bf16 mma.sync GEMM body (R9 geometry) ----------------
template<bool ATOMIC>
__device__ __forceinline__ void mma3_gemm(
    const __nv_bfloat16* __restrict__ Ahi, const __nv_bfloat16* __restrict__ Alo,
    const float* __restrict__ W, long Ksrc,
    float* __restrict__ Cout, int Cstride, const float* __restrict__ bias,
    int n0, long kbase, int nsteps)
{
    extern __shared__ char smem[];
    uint32_t sbase = smem_u32(smem);
    int t = threadIdx.x;
    int wid = t >> 5, lane = t & 31;
    int g = lane >> 2, tp = lane & 3;
    int warpM = wid >> 1, warpN = wid & 1;

    float acc[2][8][4];
#pragma unroll
    for (int a = 0; a < 2; a++)
#pragma unroll
        for (int b = 0; b < 8; b++)
#pragma unroll
            for (int c = 0; c < 4; c++) acc[a][b][c] = 0.f;

    float4 pw[4];

    auto cpasyncA = [&](long kg, uint32_t bufu) {
#pragma unroll
        for (int i = 0; i < 2; i++) {
            int c = i * 256 + t;
            int row = c >> 2, kc = c & 3;
            long gi = (long)row * Ksrc + kg + kc * 8;
            uint32_t dst = bufu + row * APITCH + kc * 16;
            CPASYNC16(dst, (const char*)(Ahi + gi));
            CPASYNC16(dst + TILE_B, (const char*)(Alo + gi));
        }
    };
    auto prefetchW = [&](long kg) {
#pragma unroll
        for (int i = 0; i < 4; i++) {
            int f = i * 256 + t;
            int row = f >> 3, kc = f & 7;
            pw[i] = *(const float4*)(W + (long)(n0 + row) * Ksrc + kg + kc * 4);
        }
    };
    auto storeW = [&](char* buf) {
#pragma unroll
        for (int i = 0; i < 4; i++) {
            int f = i * 256 + t;
            int row = f >> 3, kc = f & 7;
            float4 v = pw[i];
            __nv_bfloat162 h0 = __floats2bfloat162_rn(v.x, v.y);
            __nv_bfloat162 h1 = __floats2bfloat162_rn(v.z, v.w);
            float e0 = v.x - __bfloat162float(h0.x);
            float e1 = v.y - __bfloat162float(h0.y);
            float e2 = v.z - __bfloat162float(h1.x);
            float e3 = v.w - __bfloat162float(h1.y);
            __nv_bfloat162 l0 = __floats2bfloat162_rn(e0, e1);
            __nv_bfloat162 l1 = __floats2bfloat162_rn(e2, e3);
            *(uint2*)(buf + 2 * TILE_B + row * APITCH + kc * 8) =
                make_uint2(*(uint32_t*)&h0, *(uint32_t*)&h1);
            *(uint2*)(buf + 3 * TILE_B + row * APITCH + kc * 8) =
                make_uint2(*(uint32_t*)&l0, *(uint32_t*)&l1);
        }
    };

    const uint32_t aoff = (uint32_t)(lane & 15) * APITCH + ((lane >> 4) & 1) * 16;
    const uint32_t boff = (uint32_t)((lane & 7) + ((lane >> 4) & 1) * 8) * APITCH +
                          ((lane >> 3) & 1) * 16;

    cpasyncA(kbase, sbase);
    CPCOMMIT();
    prefetchW(kbase);
    storeW(smem);
    CPWAIT0();
    __syncthreads();

#pragma unroll 1
    for (int s = 0; s < nsteps; s++) {
        bool more = (s + 1 < nsteps);
        if (more) {
            cpasyncA(kbase + (long)(s + 1) * KSTEP, sbase + ((s + 1) & 1) * STAGE);
            CPCOMMIT();
            prefetchW(kbase + (long)(s + 1) * KSTEP);
        }
        uint32_t bufu = sbase + (s & 1) * STAGE;
        uint32_t aBase = bufu + (uint32_t)(warpM * 32) * APITCH + aoff;
        uint32_t bBase = bufu + 2 * TILE_B + (uint32_t)(warpN * 64) * APITCH + boff;

#pragma unroll
        for (int kt = 0; kt < 2; kt++) {
            uint32_t kb = kt * 32;
            uint32_t ah[2][4], al[2][4];
#pragma unroll
            for (int mt = 0; mt < 2; mt++) {
                uint32_t aa = aBase + (uint32_t)(mt * 16) * APITCH + kb;
                LDSM4(ah[mt][0], ah[mt][1], ah[mt][2], ah[mt][3], aa);
                LDSM4(al[mt][0], al[mt][1], al[mt][2], al[mt][3], aa + TILE_B);
            }
#pragma unroll
            for (int pr = 0; pr < 4; pr++) {
                uint32_t ba = bBase + (uint32_t)(pr * 16) * APITCH + kb;
                uint32_t b0, b1, b2, b3, c0r, c1r, c2r, c3r;
                LDSM4(b0, b1, b2, b3, ba);               // hi
                LDSM4(c0r, c1r, c2r, c3r, ba + TILE_B);  // lo
#pragma unroll
                for (int mt = 0; mt < 2; mt++) {
                    MMA16816(acc[mt][2 * pr],     ah[mt], b0, b1);
                    MMA16816(acc[mt][2 * pr],     ah[mt], c0r, c1r);
                    MMA16816(acc[mt][2 * pr],     al[mt], b0, b1);
                    MMA16816(acc[mt][2 * pr + 1], ah[mt], b2, b3);
                    MMA16816(acc[mt][2 * pr + 1], ah[mt], c2r, c3r);
                    MMA16816(acc[mt][2 * pr + 1], al[mt], b2, b3);
                }
            }
        }
        if (more) {
            storeW(smem + ((s + 1) & 1) * STAGE);
            CPWAIT0();
        }
        __syncthreads();
    }

#pragma unroll
    for (int mt = 0; mt < 2; mt++)
#pragma unroll
        for (int nt = 0; nt < 8; nt++) {
            int row = warpM * 32 + mt * 16 + g;
            int col = n0 + warpN * 64 + nt * 8 + tp * 2;
            if (ATOMIC) {
                atomicAdd(&Cout[(long)row * Cstride + col],           acc[mt][nt][0]);
                atomicAdd(&Cout[(long)row * Cstride + col + 1],       acc[mt][nt][1]);
                atomicAdd(&Cout[(long)(row + 8) * Cstride + col],     acc[mt][nt][2]);
                atomicAdd(&Cout[(long)(row + 8) * Cstride + col + 1], acc[mt][nt][3]);
            } else {
                Cout[(long)row * Cstride + col]           = acc[mt][nt][0] + bias[col];
                Cout[(long)row * Cstride + col + 1]       = acc[mt][nt][1] + bias[col + 1];
                Cout[(long)(row + 8) * Cstride + col]     = acc[mt][nt][2] + bias[col];
                Cout[(long)(row + 8) * Cstride + col + 1] = acc[mt][nt][3] + bias[col + 1];
            }
        }
}

// 4096 total K-steps split unevenly over 74 chunks: first 26 CTAs get 56, rest get 55.
__global__ __launch_bounds__(256, 2) void k5_mma(const float* __restrict__ w0) {
    int y = blockIdx.y;
    int nst = 55 + (y < 26 ? 1 : 0);
    long kb = ((long)y * 55 + (y < 26 ? y : 26)) * KSTEP;
    mma3_gemm<true>(g_h_hi, g_h_lo, w0, KBIG, g_acc0, Hh, nullptr,
                    blockIdx.x * 128, kb, nst);
}
__global__ __launch_bounds__(256, 2) void k7_mma(const float* __restrict__ w2,
                                                 const float* __restrict__ bb2) {
    mma3_gemm<false>(g_z1_hi, g_z1_lo, w2, Hh, g_z2, J2, bb2,
                     blockIdx.x * 128, 0, Hh / KSTEP);
}

// k6: tiled GEMV batch. Block = 16(b) x 8(j); z0 = relu(acc0+bb0) built in smem once.
__global__ __launch_bounds__(256) void k6_gemm1(const float* __restrict__ w1,
                                                const float* __restrict__ bb0,
                                                const float* __restrict__ bb1) {
    __shared__ float sz0[16][512];
    int jg = blockIdx.x, bg = blockIdx.y;
    int t = threadIdx.x, w = t >> 5, lane = t & 31;

    const float4* bz = (const float4*)bb0;
#pragma unroll
    for (int i = 0; i < 8; i++) {
        int idx = i * 256 + t;
        int row = idx >> 7, c4 = idx & 127;
        float4 av = *(const float4*)(g_acc0 + (long)(bg * 16 + row) * 512 + c4 * 4);
        float4 bv = bz[c4];
        float4 z;
        z.x = fmaxf(av.x + bv.x, 0.f);
        z.y = fmaxf(av.y + bv.y, 0.f);
        z.z = fmaxf(av.z + bv.z, 0.f);
        z.w = fmaxf(av.w + bv.w, 0.f);
        *(float4*)&sz0[row][c4 * 4] = z;
    }
    __syncthreads();

    int j = jg * 8 + w;
    float4 wreg[4];
    const float4* wrow = (const float4*)(w1 + (long)j * 512);
#pragma unroll
    for (int i = 0; i < 4; i++) wreg[i] = wrow[lane + 32 * i];
    float bj = bb1[j];

#pragma unroll 1
    for (int b = 0; b < 16; b++) {
        float acc = 0.f;
#pragma unroll
        for (int i = 0; i < 4; i++) {
            float4 zv = *(const float4*)&sz0[b][(lane + 32 * i) * 4];
            acc = fmaf(zv.x, wreg[i].x, acc);
            acc = fmaf(zv.y, wreg[i].y, acc);
            acc = fmaf(zv.z, wreg[i].z, acc);
            acc = fmaf(zv.w, wreg[i].w, acc);
        }
        acc = wsum(acc);
        if (lane == 0) {
            float v = fmaxf(acc + bj, 0.f);
            __nv_bfloat16 hv = __float2bfloat16_rn(v);
            float e = v - __bfloat162float(hv);
            int o = (bg * 16 + b) * 512 + j;
            g_z1_hi[o] = hv;
            g_z1_lo[o] = __float2bfloat16_rn(e);
        }
    }
}

// k8: coeffs = U @ V^T per batch. Vt stride 257 (conflict-free).
__global__ __launch_bounds__(256) void k8_coeffs(float* __restrict__ out) {
    __shared__ float Us[16 * 32];
    __shared__ float Vt[32 * 257];
    int b = blockIdx.x, i0 = blockIdx.y * 16, t = threadIdx.x;
    const float* src = g_z2 + (long)b * J2;
#pragma unroll
    for (int q = 0; q < 2; q++) Us[t + 256 * q] = src[i0 * 32 + t + 256 * q];
#pragma unroll
    for (int q = 0; q < 32; q++) {
        int idx = t + 256 * q;
        float v = src[8192 + idx];
        Vt[(idx & 31) * 257 + (idx >> 5)] = v;
    }
    __syncthreads();
    float acc[16];
#pragma unroll
    for (int i = 0; i < 16; i++) acc[i] = 0.f;
#pragma unroll
    for (int r = 0; r < 32; r++) {
        float v = Vt[r * 257 + t];
#pragma unroll
        for (int i = 0; i < 16; i++) acc[i] = fmaf(Us[i * 32 + r], v, acc[i]);
    }
#pragma unroll
    for (int i = 0; i < 16; i++)
        out[((long)(b * 256) + (i0 + i)) * 256 + t] = acc[i];
}

extern "C" void kernel_launch(void* const* d_in, const int* in_sizes, int n_in,
                              void* d_out, int out_size) {
    const float* x     = (const float*)d_in[0];
    const float* qw    = (const float*)d_in[1];
    const float* qb    = (const float*)d_in[2];
    const float* kw    = (const float*)d_in[3];
    const float* kb    = (const float*)d_in[4];
    const float* vw    = (const float*)d_in[5];
    const float* vb    = (const float*)d_in[6];
    const float* res_w = (const float*)d_in[7];
    const float* res_b = (const float*)d_in[8];
    const float* ln_g  = (const float*)d_in[9];
    const float* ln_b  = (const float*)d_in[10];
    const float* w0    = (const float*)d_in[11];
    const float* bb0   = (const float*)d_in[12];
    const float* w1    = (const float*)d_in[13];
    const float* bb1   = (const float*)d_in[14];
    const float* w2    = (const float*)d_in[15];
    const float* bb2   = (const float*)d_in[16];

    float* out  = (float*)d_out;
    float* outC = out;                                // coeffs_k: (B,P,P)
    float* outA = out + (long)Bb * Pp * Pp;           // attn_mean: (B,P,P)

    cudaFuncSetAttribute(k5_mma, cudaFuncAttributeMaxDynamicSharedMemorySize, SMEM_MMA);
    cudaFuncSetAttribute(k7_mma, cudaFuncAttributeMaxDynamicSharedMemorySize, SMEM_MMA);

    k01<<<128 + 512, 256>>>(x, qw, qb, kw, kb, vw, vb, res_w, res_b);
    k23<<<2048, 512>>>(ln_g, ln_b, outA);
    k5_mma<<<dim3(4, KSPLIT5), 256, SMEM_MMA>>>(w0);          // profiled slot (launch #3)
    k6_gemm1<<<dim3(64, 8), 256>>>(w1, bb0, bb1);
    k7_mma<<<dim3(J2 / 128, 1), 256, SMEM_MMA>>>(w2, bb2);
    k8_coeffs<<<dim3(Bb, Pp / 16), 256>>>(outC);
}

// round 17
// speedup vs baseline: 1.0687x; 1.0217x over previous
#include <cuda_runtime.h>
#include <cuda_bf16.h>
#include <cstdint>

#define FULLM 0xffffffffu
constexpr int Bb = 128, Pp = 256, Hh = 512;
constexpr int KBIG = Pp * Hh;        // 131072
constexpr int J2 = 2 * Pp * 32;      // 16384
constexpr float EPSF = 1e-5f;
constexpr float ALPHAc = 0.9f;
constexpr float INV16TAU = 1.0f / (16.0f * 0.3f);
constexpr float LOG2E = 1.4426950408889634f;

// ---- mma.sync GEMM config ----
constexpr int KSTEP = 32;
constexpr int KSPLIT5 = 74;               // 4x74 = 296 CTAs = exactly 2/SM on 148 SMs
constexpr int APITCH = 80;                // bytes per 32-col bf16 row (padded)
constexpr int TILE_B = 128 * APITCH;      // 10240
constexpr int STAGE = 4 * TILE_B;         // Ah, Al, Wh, Wl = 40960
constexpr int SMEM_MMA = 2 * STAGE;       // 81920

__device__ float g_av[512], g_bv[512];
__device__ float g_qc1[Bb * 8 * Pp], g_qc0[Bb * 8 * Pp];
__device__ __align__(8) float2 g_inv[Bb * 8 * Pp];    // (1/denK, 1/denV)
__device__ float g_res[Bb * Hh];
__device__ __align__(16) __nv_bfloat16 g_h_hi[(long)Bb * Pp * Hh];
__device__ __align__(16) __nv_bfloat16 g_h_lo[(long)Bb * Pp * Hh];
__device__ float g_acc0[Bb * Hh];
__device__ __align__(16) __nv_bfloat16 g_z1_hi[Bb * Hh], g_z1_lo[Bb * Hh];
__device__ float g_z2[Bb * J2];

#define MMA16816(d, a, b0v, b1v) \
    asm volatile("mma.sync.aligned.m16n8k16.row.col.f32.bf16.bf16.f32 " \
        "{%0,%1,%2,%3}, {%4,%5,%6,%7}, {%8,%9}, {%0,%1,%2,%3};" \
        : "+f"((d)[0]), "+f"((d)[1]), "+f"((d)[2]), "+f"((d)[3]) \
        : "r"((a)[0]), "r"((a)[1]), "r"((a)[2]), "r"((a)[3]), "r"(b0v), "r"(b1v))

#define LDSM4(r0, r1, r2, r3, addr) \
    asm volatile("ldmatrix.sync.aligned.m8n8.x4.shared.b16 {%0,%1,%2,%3}, [%4];" \
        : "=r"(r0), "=r"(r1), "=r"(r2), "=r"(r3) : "r"(addr))

#define CPASYNC16(dst, src) \
    asm volatile("cp.async.ca.shared.global [%0], [%1], 16;" :: "r"(dst), "l"(src))
#define CPCOMMIT() asm volatile("cp.async.commit_group;" ::: "memory")
#define CPWAIT0()  asm volatile("cp.async.wait_group 0;" ::: "memory")

__device__ __forceinline__ uint32_t smem_u32(const void* p) {
    uint32_t a;
    asm("{ .reg .u64 t; cvta.to.shared.u64 t, %1; cvt.u32.u64 %0, t; }" : "=r"(a) : "l"(p));
    return a;
}
__device__ __forceinline__ float ex2f(float x) {
    float r;
    asm("ex2.approx.f32 %0, %1;" : "=f"(r) : "f"(x));
    return r;
}
__device__ __forceinline__ float wsum(float v) {
#pragma unroll
    for (int o = 16; o; o >>= 1) v += __shfl_xor_sync(FULLM, v, o);
    return v;
}

// ---------------- K01: stats+tables (blocks 0..127) + tiled res GEMV (128..639) ----------
__global__ __launch_bounds__(256) void k01(const float* __restrict__ X,
                                           const float* __restrict__ qw, const float* __restrict__ qb,
                                           const float* __restrict__ kw, const float* __restrict__ kb,
                                           const float* __restrict__ vw, const float* __restrict__ vb,
                                           const float* __restrict__ rw, const float* __restrict__ rb) {
    __shared__ float sx[16][256];
    int bx = blockIdx.x;
    int t = threadIdx.x;
    int wid = t >> 5, lane = t & 31;

    if (bx >= 128) {   // tiled res GEMV: res[16b x 8c] per block
        int idx = bx - 128;
        int bg = idx >> 6;
        int jg = idx & 63;
#pragma unroll
        for (int i = 0; i < 4; i++) {
            int e = i * 256 + t;
            int row = e >> 6, c4 = e & 63;
            *(float4*)&sx[row][c4 * 4] =
                *(const float4*)(X + (long)(bg * 16 + row) * 256 + c4 * 4);
        }
        __syncthreads();
        int c = jg * 8 + wid;
        float4 wreg[2];
        const float4* wrow = (const float4*)(rw + (long)c * 256);
        wreg[0] = wrow[lane];
        wreg[1] = wrow[lane + 32];
        float bc = rb[c];
#pragma unroll 1
        for (int b = 0; b < 16; b++) {
            float acc = 0.f;
#pragma unroll
            for (int i = 0; i < 2; i++) {
                float4 xv = *(const float4*)&sx[b][(lane + 32 * i) * 4];
                acc = fmaf(xv.x, wreg[i].x, acc);
                acc = fmaf(xv.y, wreg[i].y, acc);
                acc = fmaf(xv.z, wreg[i].z, acc);
                acc = fmaf(xv.w, wreg[i].w, acc);
            }
            acc = wsum(acc);
            if (lane == 0) g_res[(bg * 16 + b) * 512 + c] = acc + bc;
        }
        return;
    }

    float* ss = &sx[0][0];
    int b = bx;
    int h = wid;
    int c0 = h * 64 + lane, c1 = c0 + 32;

    float qw0 = qw[c0], qw1 = qw[c1], qb0 = qb[c0], qb1 = qb[c1];
    float kw0 = kw[c0], kw1 = kw[c1], kb0 = kb[c0], kb1 = kb[c1];
    float vw0 = vw[c0], vw1 = vw[c1], vb0 = vb[c0], vb1 = vb[c1];

    float muQw = wsum(qw0 + qw1) * (1.f / 64.f), muQb = wsum(qb0 + qb1) * (1.f / 64.f);
    float muKw = wsum(kw0 + kw1) * (1.f / 64.f), muKb = wsum(kb0 + kb1) * (1.f / 64.f);
    float muVw = wsum(vw0 + vw1) * (1.f / 64.f), muVb = wsum(vb0 + vb1) * (1.f / 64.f);

    float aq0 = qw0 - muQw, aq1 = qw1 - muQw, bq0 = qb0 - muQb, bq1 = qb1 - muQb;
    float ak0 = kw0 - muKw, ak1 = kw1 - muKw, bk0 = kb0 - muKb, bk1 = kb1 - muKb;
    float av0 = vw0 - muVw, av1 = vw1 - muVw, bv0 = vb0 - muVb, bv1 = vb1 - muVb;

    float A  = wsum(aq0 * ak0 + aq1 * ak1);
    float Bt = wsum(aq0 * bk0 + aq1 * bk1);
    float C  = wsum(bq0 * ak0 + bq1 * ak1);
    float D  = wsum(bq0 * bk0 + bq1 * bk1);
    float qV2 = wsum(aq0 * aq0 + aq1 * aq1) * (1.f / 64.f);
    float qV1 = wsum(aq0 * bq0 + aq1 * bq1) * (1.f / 64.f);
    float qV0 = wsum(bq0 * bq0 + bq1 * bq1) * (1.f / 64.f);
    float kV2 = wsum(ak0 * ak0 + ak1 * ak1) * (1.f / 64.f);
    float kV1 = wsum(ak0 * bk0 + ak1 * bk1) * (1.f / 64.f);
    float kV0 = wsum(bk0 * bk0 + bk1 * bk1) * (1.f / 64.f);
    float vV2 = wsum(av0 * av0 + av1 * av1) * (1.f / 64.f);
    float vV1 = wsum(av0 * bv0 + av1 * bv1) * (1.f / 64.f);
    float vV0 = wsum(bv0 * bv0 + bv1 * bv1) * (1.f / 64.f);

    if (lane == 0) {
        float* s = &ss[h * 16];
        s[0] = A; s[1] = Bt; s[2] = C; s[3] = D;
        s[4] = qV2; s[5] = 2.f * qV1; s[6] = qV0;
        s[7] = kV2; s[8] = 2.f * kV1; s[9] = kV0;
        s[10] = vV2; s[11] = 2.f * vV1; s[12] = vV0;
    }
    if (b == 0) {
        g_av[c0] = av0; g_av[c1] = av1;
        g_bv[c0] = bv0; g_bv[c1] = bv1;
    }
    __syncthreads();

    int p = t;
    float x = X[b * 256 + p];
#pragma unroll
    for (int hh = 0; hh < 8; hh++) {
        const float* s = &ss[hh * 16];
        int base = (b * 8 + hh) * 256 + p;
        float denq = sqrtf(fmaf(x, fmaf(x, s[4], s[5]), s[6]) + EPSF);
        float inv = (INV16TAU * LOG2E) / denq;
        g_qc1[base] = fmaf(s[0], x, s[2]) * inv;
        g_qc0[base] = fmaf(s[1], x, s[3]) * inv;
        float denk = sqrtf(fmaf(x, fmaf(x, s[7], s[8]), s[9]) + EPSF);
        float denv = sqrtf(fmaf(x, fmaf(x, s[10], s[11]), s[12]) + EPSF);
        g_inv[base] = make_float2(1.f / denk, 1.f / denv);
    }
    int i = b * 256 + p;
    g_acc0[i] = 0.f;
    g_acc0[i + 32768] = 0.f;
}

// ---------------- K23: attention + fused LN(h); x in registers, float2 tables ----------
__global__ __launch_bounds__(512) void k23(const float* __restrict__ X,
                                           const float* __restrict__ lng,
                                           const float* __restrict__ lnb,
                                           float* __restrict__ outAttn) {
    __shared__ float2 sinv[2048];
    __shared__ float sav[512], sbv[512], sres[512];
    int bx = blockIdx.x;
    int t = threadIdx.x, warp = t >> 5, lane = t & 31;
    int b = bx >> 4;
    int q = (bx & 15) * 16 + warp;

    for (int i = t; i < 2048; i += 512) sinv[i] = g_inv[b * 2048 + i];
    if (t < 512) {
        sav[t] = g_av[t];
        sbv[t] = g_bv[t];
        sres[t] = g_res[b * 512 + t];
    }
    float x8[8];
#pragma unroll
    for (int i = 0; i < 8; i++) x8[i] = X[b * 256 + lane + 32 * i];
    __syncthreads();

    float macc[8];
#pragma unroll
    for (int i = 0; i < 8; i++) macc[i] = 0.f;
    float wv1arr[8], wv0arr[8];

#pragma unroll 1
    for (int h = 0; h < 8; h++) {
        int rbase = (b * 8 + h) * 256;
        float c1 = g_qc1[rbase + q];
        float c0 = g_qc0[rbase + q];
        const float2* inv = sinv + h * 256;

        float e[8];
        float Z = 0.f, S1 = 0.f, S0 = 0.f;
#pragma unroll
        for (int i = 0; i < 8; i++) {
            int k = lane + 32 * i;
            float2 iv = inv[k];
            float a = fmaf(c1, x8[i], c0) * iv.x;
            float ex = ex2f(a);
            e[i] = ex;
            Z += ex;
            float tt = ex * iv.y;
            S1 = fmaf(tt, x8[i], S1);
            S0 += tt;
        }
#pragma unroll
        for (int o = 16; o; o >>= 1) {
            Z  += __shfl_xor_sync(FULLM, Z, o);
            S1 += __shfl_xor_sync(FULLM, S1, o);
            S0 += __shfl_xor_sync(FULLM, S0, o);
        }
        float invZ = 1.0f / Z;
        wv1arr[h] = S1 * invZ;
        wv0arr[h] = S0 * invZ;
#pragma unroll
        for (int i = 0; i < 8; i++) macc[i] = fmaf(e[i], invZ, macc[i]);
    }
    float* orow = outAttn + ((long)(b * 256) + q) * 256;
#pragma unroll
    for (int i = 0; i < 8; i++) orow[lane + 32 * i] = macc[i] * 0.125f;

    // ---- fused LN over c for this (b, p=q) row ----
    float tv[16];
    float s = 0.f, qq = 0.f;
#pragma unroll
    for (int ch = 0; ch < 16; ch++) {
        int c = ch * 32 + lane;
        int hh = ch >> 1;
        float v = fmaf(sav[c], wv1arr[hh], fmaf(sbv[c], wv0arr[hh], ALPHAc * sres[c]));
        tv[ch] = v;
        s += v;
        qq = fmaf(v, v, qq);
    }
#pragma unroll
    for (int o = 16; o; o >>= 1) {
        s  += __shfl_xor_sync(FULLM, s, o);
        qq += __shfl_xor_sync(FULLM, qq, o);
    }
    float mean = s * (1.f / 512.f);
    float var = qq * (1.f / 512.f) - mean * mean;
    float r = rsqrtf(var + EPSF);

    long rowbase = ((long)(b * 256) + q) * 512;
#pragma unroll
    for (int ch = 0; ch < 16; ch++) {
        int c = ch * 32 + lane;
        float o0 = fmaf((tv[ch] - mean) * r, lng[c], lnb[c]);
        __nv_bfloat16 hv = __float2bfloat16_rn(o0);
        float e = o0 - __bfloat162float(hv);
        g_h_hi[rowbase + c] = hv;
        g_h_lo[rowbase + c] = __float2bfloat16_rn(e);
    }
}

// ---------------- 3-split bf16 mma.sync GEMM body (R9 geometry) ----------------
template<bool ATOMIC>
__device__ __forceinline__ void mma3_gemm(
    const __nv_bfloat16* __restrict__ Ahi, const __nv_bfloat16* __restrict__ Alo,
    const float* __restrict__ W, long Ksrc,
    float* __restrict__ Cout, int Cstride, const float* __restrict__ bias,
    int n0, long kbase, int nsteps)
{
    extern __shared__ char smem[];
    uint32_t sbase = smem_u32(smem);
    int t = threadIdx.x;
    int wid = t >> 5, lane = t & 31;
    int g = lane >> 2, tp = lane & 3;
    int warpM = wid >> 1, warpN = wid & 1;

    float acc[2][8][4];
#pragma unroll
    for (int a = 0; a < 2; a++)
#pragma unroll
        for (int b = 0; b < 8; b++)
#pragma unroll
            for (int c = 0; c < 4; c++) acc[a][b][c] = 0.f;

    float4 pw[4];

    auto cpasyncA = [&](long kg, uint32_t bufu) {
#pragma unroll
        for (int i = 0; i < 2; i++) {
            int c = i * 256 + t;
            int row = c >> 2, kc = c & 3;
            long gi = (long)row * Ksrc + kg + kc * 8;
            uint32_t dst = bufu + row * APITCH + kc * 16;
            CPASYNC16(dst, (const char*)(Ahi + gi));
            CPASYNC16(dst + TILE_B, (const char*)(Alo + gi));
        }
    };
    auto prefetchW = [&](long kg) {
#pragma unroll
        for (int i = 0; i < 4; i++) {
            int f = i * 256 + t;
            int row = f >> 3, kc = f & 7;
            pw[i] = *(const float4*)(W + (long)(n0 + row) * Ksrc + kg + kc * 4);
        }
    };
    auto storeW = [&](char* buf) {
#pragma unroll
        for (int i = 0; i < 4; i++) {
            int f = i * 256 + t;
            int row = f >> 3, kc = f & 7;
            float4 v = pw[i];
            __nv_bfloat162 h0 = __floats2bfloat162_rn(v.x, v.y);
            __nv_bfloat162 h1 = __floats2bfloat162_rn(v.z, v.w);
            float e0 = v.x - __bfloat162float(h0.x);
            float e1 = v.y - __bfloat162float(h0.y);
            float e2 = v.z - __bfloat162float(h1.x);
            float e3 = v.w - __bfloat162float(h1.y);
            __nv_bfloat162 l0 = __floats2bfloat162_rn(e0, e1);
            __nv_bfloat162 l1 = __floats2bfloat162_rn(e2, e3);
            *(uint2*)(buf + 2 * TILE_B + row * APITCH + kc * 8) =
                make_uint2(*(uint32_t*)&h0, *(uint32_t*)&h1);
            *(uint2*)(buf + 3 * TILE_B + row * APITCH + kc * 8) =
                make_uint2(*(uint32_t*)&l0, *(uint32_t*)&l1);
        }
    };

    const uint32_t aoff = (uint32_t)(lane & 15) * APITCH + ((lane >> 4) & 1) * 16;
    const uint32_t boff = (uint32_t)((lane & 7) + ((lane >> 4) & 1) * 8) * APITCH +
                          ((lane >> 3) & 1) * 16;

    cpasyncA(kbase, sbase);
    CPCOMMIT();
    prefetchW(kbase);
    storeW(smem);
    CPWAIT0();
    __syncthreads();

#pragma unroll 1
    for (int s = 0; s < nsteps; s++) {
        bool more = (s + 1 < nsteps);
        if (more) {
            cpasyncA(kbase + (long)(s + 1) * KSTEP, sbase + ((s + 1) & 1) * STAGE);
            CPCOMMIT();
            prefetchW(kbase + (long)(s + 1) * KSTEP);
        }
        uint32_t bufu = sbase + (s & 1) * STAGE;
        uint32_t aBase = bufu + (uint32_t)(warpM * 32) * APITCH + aoff;
        uint32_t bBase = bufu + 2 * TILE_B + (uint32_t)(warpN * 64) * APITCH + boff;

#pragma unroll
        for (int kt = 0; kt < 2; kt++) {
            uint32_t kb = kt * 32;
            uint32_t ah[2][4], al[2][4];
#pragma unroll
            for (int mt = 0; mt < 2; mt++) {
                uint32_t aa = aBase + (uint32_t)(mt * 16) * APITCH + kb;
                LDSM4(ah[mt][0], ah[mt][1], ah[mt][2], ah[mt][3], aa);
                LDSM4(al[mt][0], al[mt][1], al[mt][2], al[mt][3], aa + TILE_B);
            }
#pragma unroll
            for (int pr = 0; pr < 4; pr++) {
                uint32_t ba = bBase + (uint32_t)(pr * 16) * APITCH + kb;
                uint32_t b0, b1, b2, b3, c0r, c1r, c2r, c3r;
                LDSM4(b0, b1, b2, b3, ba);               // hi
                LDSM4(c0r, c1r, c2r, c3r, ba + TILE_B);  // lo
#pragma unroll
                for (int mt = 0; mt < 2; mt++) {
                    MMA16816(acc[mt][2 * pr],     ah[mt], b0, b1);
                    MMA16816(acc[mt][2 * pr],     ah[mt], c0r, c1r);
                    MMA16816(acc[mt][2 * pr],     al[mt], b0, b1);
                    MMA16816(acc[mt][2 * pr + 1], ah[mt], b2, b3);
                    MMA16816(acc[mt][2 * pr + 1], ah[mt], c2r, c3r);
                    MMA16816(acc[mt][2 * pr + 1], al[mt], b2, b3);
                }
            }
        }
        if (more) {
            storeW(smem + ((s + 1) & 1) * STAGE);
            CPWAIT0();
        }
        __syncthreads();
    }

#pragma unroll
    for (int mt = 0; mt < 2; mt++)
#pragma unroll
        for (int nt = 0; nt < 8; nt++) {
            int row = warpM * 32 + mt * 16 + g;
            int col = n0 + warpN * 64 + nt * 8 + tp * 2;
            if (ATOMIC) {
                atomicAdd(&Cout[(long)row * Cstride + col],           acc[mt][nt][0]);
                atomicAdd(&Cout[(long)row * Cstride + col + 1],       acc[mt][nt][1]);
                atomicAdd(&Cout[(long)(row + 8) * Cstride + col],     acc[mt][nt][2]);
                atomicAdd(&Cout[(long)(row + 8) * Cstride + col + 1], acc[mt][nt][3]);
            } else {
                Cout[(long)row * Cstride + col]           = acc[mt][nt][0] + bias[col];
                Cout[(long)row * Cstride + col + 1]       = acc[mt][nt][1] + bias[col + 1];
                Cout[(long)(row + 8) * Cstride + col]     = acc[mt][nt][2] + bias[col];
                Cout[(long)(row + 8) * Cstride + col + 1] = acc[mt][nt][3] + bias[col + 1];
            }
        }
}

// 4096 total K-steps split unevenly over 74 chunks: first 26 CTAs get 56, rest get 55.
__global__ __launch_bounds__(256, 2) void k5_mma(const float* __restrict__ w0) {
    int y = blockIdx.y;
    int nst = 55 + (y < 26 ? 1 : 0);
    long kb = ((long)y * 55 + (y < 26 ? y : 26)) * KSTEP;
    mma3_gemm<true>(g_h_hi, g_h_lo, w0, KBIG, g_acc0, Hh, nullptr,
                    blockIdx.x * 128, kb, nst);
}
__global__ __launch_bounds__(256, 2) void k7_mma(const float* __restrict__ w2,
                                                 const float* __restrict__ bb2) {
    mma3_gemm<false>(g_z1_hi, g_z1_lo, w2, Hh, g_z2, J2, bb2,
                     blockIdx.x * 128, 0, Hh / KSTEP);
}

// k6: tiled GEMV batch, batched reductions. Block = 16(b) x 8(j).
__global__ __launch_bounds__(256) void k6_gemm1(const float* __restrict__ w1,
                                                const float* __restrict__ bb0,
                                                const float* __restrict__ bb1) {
    __shared__ float sz0[16][512];
    int jg = blockIdx.x, bg = blockIdx.y;
    int t = threadIdx.x, w = t >> 5, lane = t & 31;

    const float4* bz = (const float4*)bb0;
#pragma unroll
    for (int i = 0; i < 8; i++) {
        int idx = i * 256 + t;
        int row = idx >> 7, c4 = idx & 127;
        float4 av = *(const float4*)(g_acc0 + (long)(bg * 16 + row) * 512 + c4 * 4);
        float4 bv = bz[c4];
        float4 z;
        z.x = fmaxf(av.x + bv.x, 0.f);
        z.y = fmaxf(av.y + bv.y, 0.f);
        z.z = fmaxf(av.z + bv.z, 0.f);
        z.w = fmaxf(av.w + bv.w, 0.f);
        *(float4*)&sz0[row][c4 * 4] = z;
    }
    __syncthreads();

    int j = jg * 8 + w;
    float4 wreg[4];
    const float4* wrow = (const float4*)(w1 + (long)j * 512);
#pragma unroll
    for (int i = 0; i < 4; i++) wreg[i] = wrow[lane + 32 * i];
    float bj = bb1[j];

    float accv[16];
#pragma unroll
    for (int b = 0; b < 16; b++) accv[b] = 0.f;
#pragma unroll
    for (int i = 0; i < 4; i++) {
        float4 wv = wreg[i];
#pragma unroll
        for (int b = 0; b < 16; b++) {
            float4 zv = *(const float4*)&sz0[b][(lane + 32 * i) * 4];
            accv[b] = fmaf(zv.x, wv.x, accv[b]);
            accv[b] = fmaf(zv.y, wv.y, accv[b]);
            accv[b] = fmaf(zv.z, wv.z, accv[b]);
            accv[b] = fmaf(zv.w, wv.w, accv[b]);
        }
    }
#pragma unroll
    for (int o = 16; o; o >>= 1)
#pragma unroll
        for (int b = 0; b < 16; b++)
            accv[b] += __shfl_xor_sync(FULLM, accv[b], o);
    if (lane == 0) {
#pragma unroll
        for (int b = 0; b < 16; b++) {
            float v = fmaxf(accv[b] + bj, 0.f);
            __nv_bfloat16 hv = __float2bfloat16_rn(v);
            float e = v - __bfloat162float(hv);
            int o = (bg * 16 + b) * 512 + j;
            g_z1_hi[o] = hv;
            g_z1_lo[o] = __float2bfloat16_rn(e);
        }
    }
}

// k8: coeffs = U @ V^T per batch. Vt stride 257 (conflict-free).
__global__ __launch_bounds__(256) void k8_coeffs(float* __restrict__ out) {
    __shared__ float Us[16 * 32];
    __shared__ float Vt[32 * 257];
    int b = blockIdx.x, i0 = blockIdx.y * 16, t = threadIdx.x;
    const float* src = g_z2 + (long)b * J2;
#pragma unroll
    for (int q = 0; q < 2; q++) Us[t + 256 * q] = src[i0 * 32 + t + 256 * q];
#pragma unroll
    for (int q = 0; q < 32; q++) {
        int idx = t + 256 * q;
        float v = src[8192 + idx];
        Vt[(idx & 31) * 257 + (idx >> 5)] = v;
    }
    __syncthreads();
    float acc[16];
#pragma unroll
    for (int i = 0; i < 16; i++) acc[i] = 0.f;
#pragma unroll
    for (int r = 0; r < 32; r++) {
        float v = Vt[r * 257 + t];
#pragma unroll
        for (int i = 0; i < 16; i++) acc[i] = fmaf(Us[i * 32 + r], v, acc[i]);
    }
#pragma unroll
    for (int i = 0; i < 16; i++)
        out[((long)(b * 256) + (i0 + i)) * 256 + t] = acc[i];
}

extern "C" void kernel_launch(void* const* d_in, const int* in_sizes, int n_in,
                              void* d_out, int out_size) {
    const float* x     = (const float*)d_in[0];
    const float* qw    = (const float*)d_in[1];
    const float* qb    = (const float*)d_in[2];
    const float* kw    = (const float*)d_in[3];
    const float* kb    = (const float*)d_in[4];
    const float* vw    = (const float*)d_in[5];
    const float* vb    = (const float*)d_in[6];
    const float* res_w = (const float*)d_in[7];
    const float* res_b = (const float*)d_in[8];
    const float* ln_g  = (const float*)d_in[9];
    const float* ln_b  = (const float*)d_in[10];
    const float* w0    = (const float*)d_in[11];
    const float* bb0   = (const float*)d_in[12];
    const float* w1    = (const float*)d_in[13];
    const float* bb1   = (const float*)d_in[14];
    const float* w2    = (const float*)d_in[15];
    const float* bb2   = (const float*)d_in[16];

    float* out  = (float*)d_out;
    float* outC = out;                                // coeffs_k: (B,P,P)
    float* outA = out + (long)Bb * Pp * Pp;           // attn_mean: (B,P,P)

    cudaFuncSetAttribute(k5_mma, cudaFuncAttributeMaxDynamicSharedMemorySize, SMEM_MMA);
    cudaFuncSetAttribute(k7_mma, cudaFuncAttributeMaxDynamicSharedMemorySize, SMEM_MMA);

    k01<<<128 + 512, 256>>>(x, qw, qb, kw, kb, vw, vb, res_w, res_b);
    k23<<<2048, 512>>>(x, ln_g, ln_b, outA);
    k5_mma<<<dim3(4, KSPLIT5), 256, SMEM_MMA>>>(w0);          // profiled slot (launch #3)
    k6_gemm1<<<dim3(64, 8), 256>>>(w1, bb0, bb1);
    k7_mma<<<dim3(J2 / 128, 1), 256, SMEM_MMA>>>(w2, bb2);
    k8_coeffs<<<dim3(Bb, Pp / 16), 256>>>(outC);
}